// round 10
// baseline (speedup 1.0000x reference)
#include <cuda_runtime.h>
#include <cuda_fp16.h>

#define NN 256
#define SS 64
#define BB 1024
#define UNFOLDS 12
#define FAST_STEPS 11          // steps 0..10 f16x2 tanh; step 11 full fp32
#define TB 7                   // batches per CTA (147 CTAs cover 1024 with clamp)
#define GRID 147
#define NPAIR 128              // i-pairs total
#define NQUAD 64               // i-quads total (4 i's each)
#define QPG 32                 // quads per i-group (2 groups)
#define FBLK 16                // fast blocks of 2 quads (8 i's) per group

// Scratch (device globals — no allocations allowed). Padded rows for prefetch overrun.
__device__ uint4  g_abq[(NQUAD + 8) * NN];  // [quad][j] {a2_p0, b2_p0, a2_p1, b2_p1} f16x2
__device__ uint4  g_w16[(NQUAD + 8) * NN];  // [quad][j] {we2_p0, we2_p1, |we2_p0|, |we2_p1|} f16x2
__device__ float4 g_weq[(NQUAD + 8) * NN];  // [quad][j] {hwe_i0..i3} f32 (colsums + fp32 step)
__device__ float4 g_abf[(NPAIR + 8) * NN];  // [pair][j] {a_lo, a_hi, b_lo, b_hi} f32
__device__ float4 g_sparams[SS * NN];       // sensory {a, b, we, wsp} f32
__device__ float  g_sum_hw[NN];
__device__ float  g_sum_hwe[NN];
__device__ float  g_cmt[NN];
__device__ float  g_gl[NN];
__device__ float  g_gv[NN];

__device__ __forceinline__ float tanh_fast(float x) {
    float t;
    asm("tanh.approx.f32 %0, %1;" : "=f"(t) : "f"(x));
    return t;
}

__device__ __forceinline__ float softplus_f(float x) {
    return log1pf(expf(x));
}

// One 8-i block (4 pairs), one batch row:
//   4x { arg2 = a2*v2 + b2 (HFMA2); t2 = tanh.f16x2 }           -> 4 XU ops
//   n16 = sum we2*t2 over 4 pairs (HMUL2 + 3 HFMA2, f16x2)
//   d16 = sum |we2|*t2 over 4 pairs
//   convert block partials (4 F2F) and fold into scalar f32 accumulators.
// F2F amortized: 1 per pair instead of 2.
__device__ __forceinline__ void proc_block16(uint4 vh, uint4 cab0, uint4 cab1,
                                             uint4 cw0, uint4 cw1,
                                             float& num, float& den) {
    unsigned a, t0, t1, t2, t3, n16, d16;
    asm("fma.rn.f16x2 %0, %1, %2, %3;" : "=r"(a) : "r"(cab0.x), "r"(vh.x), "r"(cab0.y));
    asm("tanh.approx.f16x2 %0, %1;" : "=r"(t0) : "r"(a));
    asm("fma.rn.f16x2 %0, %1, %2, %3;" : "=r"(a) : "r"(cab0.z), "r"(vh.y), "r"(cab0.w));
    asm("tanh.approx.f16x2 %0, %1;" : "=r"(t1) : "r"(a));
    asm("fma.rn.f16x2 %0, %1, %2, %3;" : "=r"(a) : "r"(cab1.x), "r"(vh.z), "r"(cab1.y));
    asm("tanh.approx.f16x2 %0, %1;" : "=r"(t2) : "r"(a));
    asm("fma.rn.f16x2 %0, %1, %2, %3;" : "=r"(a) : "r"(cab1.z), "r"(vh.w), "r"(cab1.w));
    asm("tanh.approx.f16x2 %0, %1;" : "=r"(t3) : "r"(a));

    asm("mul.rn.f16x2 %0, %1, %2;"     : "=r"(n16) : "r"(cw0.x), "r"(t0));
    asm("fma.rn.f16x2 %0, %1, %2, %0;" : "+r"(n16) : "r"(cw0.y), "r"(t1));
    asm("fma.rn.f16x2 %0, %1, %2, %0;" : "+r"(n16) : "r"(cw1.x), "r"(t2));
    asm("fma.rn.f16x2 %0, %1, %2, %0;" : "+r"(n16) : "r"(cw1.y), "r"(t3));

    asm("mul.rn.f16x2 %0, %1, %2;"     : "=r"(d16) : "r"(cw0.z), "r"(t0));
    asm("fma.rn.f16x2 %0, %1, %2, %0;" : "+r"(d16) : "r"(cw0.w), "r"(t1));
    asm("fma.rn.f16x2 %0, %1, %2, %0;" : "+r"(d16) : "r"(cw1.z), "r"(t2));
    asm("fma.rn.f16x2 %0, %1, %2, %0;" : "+r"(d16) : "r"(cw1.w), "r"(t3));

    float nlo, nhi, dlo, dhi;
    asm("{ .reg .b16 l, h;\n\t"
        "  mov.b32 {l, h}, %2;\n\t"
        "  cvt.f32.f16 %0, l;\n\t"
        "  cvt.f32.f16 %1, h; }"
        : "=f"(nlo), "=f"(nhi) : "r"(n16));
    asm("{ .reg .b16 l, h;\n\t"
        "  mov.b32 {l, h}, %2;\n\t"
        "  cvt.f32.f16 %0, l;\n\t"
        "  cvt.f32.f16 %1, h; }"
        : "=f"(dlo), "=f"(dhi) : "r"(d16));
    num += nlo + nhi;
    den += dlo + dhi;
}

// ---------------------------------------------------------------------------
// Pack recurrent params per i-quad (i = 4q..4q+3):
// sigmoid(s*(v-m)) = 0.5*(1 + tanh(0.5*s*v - 0.5*s*m)); hw = 0.5*softplus(w)*mask
// hwe = hw*erev (erev = ±1 -> hw = |hwe|)
// ---------------------------------------------------------------------------
__global__ void k_prep(const float* __restrict__ w, const float* __restrict__ sigma,
                       const float* __restrict__ mu, const float* __restrict__ erev,
                       const float* __restrict__ mask) {
    int q = blockIdx.x, j = threadIdx.x;
    float a[4], b[4], e[4];
    #pragma unroll
    for (int k = 0; k < 4; k++) {
        int x = (4 * q + k) * NN + j;
        a[k] = 0.5f * sigma[x];
        b[k] = -a[k] * mu[x];
        e[k] = 0.5f * softplus_f(w[x]) * mask[x] * erev[x];
    }
    __half2 A0 = __floats2half2_rn(a[0], a[1]);
    __half2 B0 = __floats2half2_rn(b[0], b[1]);
    __half2 A1 = __floats2half2_rn(a[2], a[3]);
    __half2 B1 = __floats2half2_rn(b[2], b[3]);
    uint4 abq;
    abq.x = *reinterpret_cast<unsigned*>(&A0);
    abq.y = *reinterpret_cast<unsigned*>(&B0);
    abq.z = *reinterpret_cast<unsigned*>(&A1);
    abq.w = *reinterpret_cast<unsigned*>(&B1);
    g_abq[q * NN + j] = abq;

    __half2 W0 = __floats2half2_rn(e[0], e[1]);
    __half2 W1 = __floats2half2_rn(e[2], e[3]);
    uint4 w16;
    w16.x = *reinterpret_cast<unsigned*>(&W0);
    w16.y = *reinterpret_cast<unsigned*>(&W1);
    w16.z = w16.x & 0x7FFF7FFFu;
    w16.w = w16.y & 0x7FFF7FFFu;
    g_w16[q * NN + j] = w16;

    g_weq[q * NN + j] = make_float4(e[0], e[1], e[2], e[3]);
    g_abf[(2 * q)     * NN + j] = make_float4(a[0], a[1], b[0], b[1]);
    g_abf[(2 * q + 1) * NN + j] = make_float4(a[2], a[3], b[2], b[3]);
}

__global__ void k_sprep(const float* __restrict__ sw, const float* __restrict__ ssig,
                        const float* __restrict__ smu, const float* __restrict__ serev,
                        const float* __restrict__ smask) {
    int s = blockIdx.x, j = threadIdx.x;
    int idx = s * NN + j;
    float wsp = softplus_f(sw[idx]) * smask[idx];
    float a   = 0.5f * ssig[idx];
    g_sparams[idx] = make_float4(a, -a * smu[idx], wsp * serev[idx], wsp);
}

__global__ void k_colsums(const float* __restrict__ gleak, const float* __restrict__ vleak,
                          const float* __restrict__ cm) {
    int j = threadIdx.x;
    float shw = 0.f, shwe = 0.f;
    #pragma unroll 8
    for (int q = 0; q < NQUAD; q++) {
        float4 e = g_weq[q * NN + j];
        shwe += (e.x + e.y) + (e.z + e.w);
        shw  += (fabsf(e.x) + fabsf(e.y)) + (fabsf(e.z) + fabsf(e.w));
    }
    g_sum_hw[j]  = shw;
    g_sum_hwe[j] = shwe;
    float gl = softplus_f(gleak[j]);
    g_gl[j]  = gl;
    g_gv[j]  = gl * vleak[j];
    g_cmt[j] = softplus_f(cm[j]) * (float)UNFOLDS;
}

// ---------------------------------------------------------------------------
// Main: 147 CTAs x 512 threads. CTA c owns batches [c*7, c*7+7) (last CTA
// clamps loads and guards stores). 2 i-groups of 256 j-threads each:
// group ig accumulates over pre-neurons i in [ig*128, ig*128+128) for ALL 7
// batches; partials merged via SMEM; group 0 owns batches 0-3, group 1 owns 4-6.
// Steps 0..10: f16x2 tanh + f16 block-partials; step 11: full fp32.
// ---------------------------------------------------------------------------
__global__ void __launch_bounds__(512, 1) k_main(const float* __restrict__ inputs,
                                                 const float* __restrict__ state,
                                                 float* __restrict__ out) {
    __shared__ float  v_f[TB][NN];       // canonical fp32 state
    __shared__ __half v_h[TB][NN];       // rounded copy for HFMA2 args
    __shared__ float2 part[TB][NN];      // cross-group partial {num, den}
    __shared__ float  xin[TB][SS];

    int tid = threadIdx.x;
    int ig  = tid >> 8;          // 0 or 1
    int j   = tid & 255;
    int b0  = blockIdx.x * TB;
    int own_base = ig ? 4 : 0;
    int own_cnt  = ig ? 3 : 4;
    int oth_base = ig ? 0 : 4;
    int oth_cnt  = ig ? 4 : 3;

    // inputs: 7 rows x 64 = 448 floats (clamped for the edge CTA)
    if (tid < TB * SS) xin[tid >> 6][tid & 63] = inputs[min(b0 * SS + tid, BB * SS - 1)];

    // state: 1792 floats (clamped)
    for (int idx = tid; idx < TB * NN; idx += 512) {
        float v = state[min(b0 * NN + idx, BB * NN - 1)];
        int bb = idx >> 8, jj = idx & 255;
        v_f[bb][jj] = v;
        v_h[bb][jj] = __float2half_rn(v);
    }
    __syncthreads();

    // --- sensory pass (step-invariant) for owned batches (<=4) ---
    float ncr[4], dcr[4];
    {
        float sn[4] = {0.f, 0.f, 0.f, 0.f}, sd[4] = {0.f, 0.f, 0.f, 0.f};
        #pragma unroll 2
        for (int s = 0; s < SS; s++) {
            float4 q = g_sparams[s * NN + j];
            #pragma unroll
            for (int k = 0; k < 4; k++) {
                int bx = own_base + min(k, own_cnt - 1);   // clamp keeps loop uniform
                float t  = tanh_fast(fmaf(q.x, xin[bx][s], q.y));
                float sg = fmaf(0.5f, t, 0.5f);
                sn[k] = fmaf(q.z, sg, sn[k]);
                sd[k] = fmaf(q.w, sg, sd[k]);
            }
        }
        float gv = g_gv[j], she = g_sum_hwe[j], gl = g_gl[j], shw = g_sum_hw[j];
        float cmt0 = g_cmt[j];
        #pragma unroll
        for (int k = 0; k < 4; k++) {
            ncr[k] = gv + she + sn[k];
            dcr[k] = cmt0 + gl + shw + sd[k] + 1e-8f;
        }
    }
    float cmt = g_cmt[j];

    const int Q0 = ig * QPG;            // first quad of this group
    const int P0 = ig * (NPAIR / 2);    // first pair
    const int ibase = ig * (NN / 2);    // first pre-neuron
    const uint4*  ABQ = g_abq + Q0 * NN + j;
    const uint4*  W16 = g_w16 + Q0 * NN + j;
    const float4* WEQ = g_weq + Q0 * NN + j;
    const float4* ABF = g_abf + P0 * NN + j;

    for (int step = 0; step < UNFOLDS; step++) {
        float num[TB], den[TB];
        #pragma unroll
        for (int b = 0; b < TB; b++) { num[b] = 0.f; den[b] = 0.f; }

        if (step < FAST_STEPS) {
            // ---------- fast f16x2 path ----------
            // prefetch block 0 (2 quads)
            uint4 ab0 = ABQ[0], ab1 = ABQ[NN];
            uint4 w0  = W16[0], w1  = W16[NN];

            for (int blk = 0; blk < FBLK; blk++) {
                uint4 cab0 = ab0, cab1 = ab1, cw0 = w0, cw1 = w1;

                // prefetch next block (padded rows absorb the overrun)
                ab0 = ABQ[((blk + 1) * 2    ) * NN];
                ab1 = ABQ[((blk + 1) * 2 + 1) * NN];
                w0  = W16[((blk + 1) * 2    ) * NN];
                w1  = W16[((blk + 1) * 2 + 1) * NN];

                #pragma unroll
                for (int b = 0; b < TB; b++) {
                    // 8 halves (4 pairs) = one broadcast LDS.128
                    uint4 vh = *reinterpret_cast<const uint4*>(&v_h[b][ibase + blk * 8]);
                    proc_block16(vh, cab0, cab1, cw0, cw1, num[b], den[b]);
                }
            }
        } else {
            // ---------- accurate fp32 path (last step) ----------
            #pragma unroll 2
            for (int q = 0; q < QPG; q++) {            // one quad (4 i) per iter
                float4 a0 = ABF[(q * 2) * NN];
                float4 a1 = ABF[(q * 2 + 1) * NN];
                float4 e  = WEQ[q * NN];
                #pragma unroll
                for (int b = 0; b < TB; b++) {
                    float4 v = *reinterpret_cast<const float4*>(&v_f[b][ibase + q * 4]);
                    float t0 = tanh_fast(fmaf(a0.x, v.x, a0.z));
                    float t1 = tanh_fast(fmaf(a0.y, v.y, a0.w));
                    float t2 = tanh_fast(fmaf(a1.x, v.z, a1.z));
                    float t3 = tanh_fast(fmaf(a1.y, v.w, a1.w));
                    num[b] = fmaf(e.x, t0, num[b]); den[b] = fmaf(fabsf(e.x), t0, den[b]);
                    num[b] = fmaf(e.y, t1, num[b]); den[b] = fmaf(fabsf(e.y), t1, den[b]);
                    num[b] = fmaf(e.z, t2, num[b]); den[b] = fmaf(fabsf(e.z), t2, den[b]);
                    num[b] = fmaf(e.w, t3, num[b]); den[b] = fmaf(fabsf(e.w), t3, den[b]);
                }
            }
        }

        // write partials for batches the OTHER group owns
        #pragma unroll
        for (int k = 0; k < 4; k++)
            if (k < oth_cnt)
                part[oth_base + k][j] = make_float2(num[oth_base + k], den[oth_base + k]);
        __syncthreads();

        // owned batches: merge partials, update state
        #pragma unroll
        for (int k = 0; k < 4; k++) {
            if (k < own_cnt) {
                int b = own_base + k;
                float2 o = part[b][j];
                float n = num[b] + o.x;
                float d = den[b] + o.y;
                float vn = (fmaf(cmt, v_f[b][j], ncr[k]) + n) / (d + dcr[k]);
                v_f[b][j] = vn;
                v_h[b][j] = __float2half_rn(vn);
            }
        }
        __syncthreads();
    }

    // owner writes its rows (guarded for the edge CTA)
    #pragma unroll
    for (int k = 0; k < 4; k++) {
        if (k < own_cnt) {
            int b = own_base + k;
            if (b0 + b < BB) out[(b0 + b) * NN + j] = v_f[b][j];
        }
    }
}

extern "C" void kernel_launch(void* const* d_in, const int* in_sizes, int n_in,
                              void* d_out, int out_size) {
    const float* inputs = (const float*)d_in[0];
    const float* state  = (const float*)d_in[1];
    const float* gleak  = (const float*)d_in[2];
    const float* vleak  = (const float*)d_in[3];
    const float* cm     = (const float*)d_in[4];
    const float* w      = (const float*)d_in[5];
    const float* sigma  = (const float*)d_in[6];
    const float* mu     = (const float*)d_in[7];
    const float* erev   = (const float*)d_in[8];
    const float* sw     = (const float*)d_in[9];
    const float* ssig   = (const float*)d_in[10];
    const float* smu    = (const float*)d_in[11];
    const float* serev  = (const float*)d_in[12];
    const float* mask   = (const float*)d_in[13];
    const float* smask  = (const float*)d_in[14];
    float* out = (float*)d_out;

    k_prep   <<<NQUAD, NN>>>(w, sigma, mu, erev, mask);
    k_sprep  <<<SS, NN>>>(sw, ssig, smu, serev, smask);
    k_colsums<<<1,  NN>>>(gleak, vleak, cm);
    k_main   <<<GRID, 512>>>(inputs, state, out);
}

// round 11
// speedup vs baseline: 1.0452x; 1.0452x over previous
#include <cuda_runtime.h>
#include <cuda_fp16.h>

#define NN 256
#define SS 64
#define BB 1024
#define UNFOLDS 12
#define FAST_STEPS 11          // steps 0..10 f16x2 tanh; step 11 full fp32
#define TB 7                   // batches per CTA (147 CTAs cover 1024 with clamp)
#define GRID 147
#define NPAIR 128              // i-pairs total
#define NQUAD 64               // i-quads total (4 i's each)
#define NGRP 4                 // i-split groups per CTA
#define QPG (NQUAD / NGRP)     // 16 quads per group
#define FBLK (QPG / 2)         // 8 fast blocks of 2 quads (8 i's) per group

// Scratch (device globals — no allocations allowed).
__device__ uint4  g_abq[NQUAD * NN];  // [quad][j] {a2_p0, b2_p0, a2_p1, b2_p1} f16x2
__device__ uint4  g_w16[NQUAD * NN];  // [quad][j] {we2_p0, we2_p1, |we2_p0|, |we2_p1|} f16x2
__device__ float4 g_weq[NQUAD * NN];  // [quad][j] {hwe_i0..i3} f32 (colsums + fp32 step)
__device__ float4 g_abf[NPAIR * NN];  // [pair][j] {a_lo, a_hi, b_lo, b_hi} f32
__device__ float4 g_sparams[SS * NN]; // sensory {a, b, we, wsp} f32
__device__ float  g_sum_hw[NN];
__device__ float  g_sum_hwe[NN];
__device__ float  g_cmt[NN];
__device__ float  g_gl[NN];
__device__ float  g_gv[NN];

__device__ __forceinline__ float tanh_fast(float x) {
    float t;
    asm("tanh.approx.f32 %0, %1;" : "=f"(t) : "f"(x));
    return t;
}

__device__ __forceinline__ float softplus_f(float x) {
    return log1pf(expf(x));
}

// One 8-i block (4 pairs), one batch row:
//   4x { arg2 = a2*v2 + b2 (HFMA2); t2 = tanh.f16x2 }
//   n16/d16 = f16x2 block partial sums; 4 F2F amortized; fold into f32 scalars.
__device__ __forceinline__ void proc_block16(uint4 vh, uint4 cab0, uint4 cab1,
                                             uint4 cw0, uint4 cw1,
                                             float& num, float& den) {
    unsigned a, t0, t1, t2, t3, n16, d16;
    asm("fma.rn.f16x2 %0, %1, %2, %3;" : "=r"(a) : "r"(cab0.x), "r"(vh.x), "r"(cab0.y));
    asm("tanh.approx.f16x2 %0, %1;" : "=r"(t0) : "r"(a));
    asm("fma.rn.f16x2 %0, %1, %2, %3;" : "=r"(a) : "r"(cab0.z), "r"(vh.y), "r"(cab0.w));
    asm("tanh.approx.f16x2 %0, %1;" : "=r"(t1) : "r"(a));
    asm("fma.rn.f16x2 %0, %1, %2, %3;" : "=r"(a) : "r"(cab1.x), "r"(vh.z), "r"(cab1.y));
    asm("tanh.approx.f16x2 %0, %1;" : "=r"(t2) : "r"(a));
    asm("fma.rn.f16x2 %0, %1, %2, %3;" : "=r"(a) : "r"(cab1.z), "r"(vh.w), "r"(cab1.w));
    asm("tanh.approx.f16x2 %0, %1;" : "=r"(t3) : "r"(a));

    asm("mul.rn.f16x2 %0, %1, %2;"     : "=r"(n16) : "r"(cw0.x), "r"(t0));
    asm("fma.rn.f16x2 %0, %1, %2, %0;" : "+r"(n16) : "r"(cw0.y), "r"(t1));
    asm("fma.rn.f16x2 %0, %1, %2, %0;" : "+r"(n16) : "r"(cw1.x), "r"(t2));
    asm("fma.rn.f16x2 %0, %1, %2, %0;" : "+r"(n16) : "r"(cw1.y), "r"(t3));

    asm("mul.rn.f16x2 %0, %1, %2;"     : "=r"(d16) : "r"(cw0.z), "r"(t0));
    asm("fma.rn.f16x2 %0, %1, %2, %0;" : "+r"(d16) : "r"(cw0.w), "r"(t1));
    asm("fma.rn.f16x2 %0, %1, %2, %0;" : "+r"(d16) : "r"(cw1.z), "r"(t2));
    asm("fma.rn.f16x2 %0, %1, %2, %0;" : "+r"(d16) : "r"(cw1.w), "r"(t3));

    float nlo, nhi, dlo, dhi;
    asm("{ .reg .b16 l, h;\n\t"
        "  mov.b32 {l, h}, %2;\n\t"
        "  cvt.f32.f16 %0, l;\n\t"
        "  cvt.f32.f16 %1, h; }"
        : "=f"(nlo), "=f"(nhi) : "r"(n16));
    asm("{ .reg .b16 l, h;\n\t"
        "  mov.b32 {l, h}, %2;\n\t"
        "  cvt.f32.f16 %0, l;\n\t"
        "  cvt.f32.f16 %1, h; }"
        : "=f"(dlo), "=f"(dhi) : "r"(d16));
    num += nlo + nhi;
    den += dlo + dhi;
}

// ---------------------------------------------------------------------------
// Pack recurrent params per i-quad (i = 4q..4q+3).
// ---------------------------------------------------------------------------
__global__ void k_prep(const float* __restrict__ w, const float* __restrict__ sigma,
                       const float* __restrict__ mu, const float* __restrict__ erev,
                       const float* __restrict__ mask) {
    int q = blockIdx.x, j = threadIdx.x;
    float a[4], b[4], e[4];
    #pragma unroll
    for (int k = 0; k < 4; k++) {
        int x = (4 * q + k) * NN + j;
        a[k] = 0.5f * sigma[x];
        b[k] = -a[k] * mu[x];
        e[k] = 0.5f * softplus_f(w[x]) * mask[x] * erev[x];
    }
    __half2 A0 = __floats2half2_rn(a[0], a[1]);
    __half2 B0 = __floats2half2_rn(b[0], b[1]);
    __half2 A1 = __floats2half2_rn(a[2], a[3]);
    __half2 B1 = __floats2half2_rn(b[2], b[3]);
    uint4 abq;
    abq.x = *reinterpret_cast<unsigned*>(&A0);
    abq.y = *reinterpret_cast<unsigned*>(&B0);
    abq.z = *reinterpret_cast<unsigned*>(&A1);
    abq.w = *reinterpret_cast<unsigned*>(&B1);
    g_abq[q * NN + j] = abq;

    __half2 W0 = __floats2half2_rn(e[0], e[1]);
    __half2 W1 = __floats2half2_rn(e[2], e[3]);
    uint4 w16;
    w16.x = *reinterpret_cast<unsigned*>(&W0);
    w16.y = *reinterpret_cast<unsigned*>(&W1);
    w16.z = w16.x & 0x7FFF7FFFu;
    w16.w = w16.y & 0x7FFF7FFFu;
    g_w16[q * NN + j] = w16;

    g_weq[q * NN + j] = make_float4(e[0], e[1], e[2], e[3]);
    g_abf[(2 * q)     * NN + j] = make_float4(a[0], a[1], b[0], b[1]);
    g_abf[(2 * q + 1) * NN + j] = make_float4(a[2], a[3], b[2], b[3]);
}

__global__ void k_sprep(const float* __restrict__ sw, const float* __restrict__ ssig,
                        const float* __restrict__ smu, const float* __restrict__ serev,
                        const float* __restrict__ smask) {
    int s = blockIdx.x, j = threadIdx.x;
    int idx = s * NN + j;
    float wsp = softplus_f(sw[idx]) * smask[idx];
    float a   = 0.5f * ssig[idx];
    g_sparams[idx] = make_float4(a, -a * smu[idx], wsp * serev[idx], wsp);
}

__global__ void k_colsums(const float* __restrict__ gleak, const float* __restrict__ vleak,
                          const float* __restrict__ cm) {
    int j = threadIdx.x;
    float shw = 0.f, shwe = 0.f;
    #pragma unroll 8
    for (int q = 0; q < NQUAD; q++) {
        float4 e = g_weq[q * NN + j];
        shwe += (e.x + e.y) + (e.z + e.w);
        shw  += (fabsf(e.x) + fabsf(e.y)) + (fabsf(e.z) + fabsf(e.w));
    }
    g_sum_hw[j]  = shw;
    g_sum_hwe[j] = shwe;
    float gl = softplus_f(gleak[j]);
    g_gl[j]  = gl;
    g_gv[j]  = gl * vleak[j];
    g_cmt[j] = softplus_f(cm[j]) * (float)UNFOLDS;
}

// SMEM layout (dynamic, 70 KB)
#define SM_VF   0
#define SM_VH   (TB * NN * 4)                    // 7168
#define SM_XIN  (SM_VH + TB * NN * 2)            // 10752
#define SM_PART (SM_XIN + TB * SS * 4)           // 12544
#define SM_TOTAL (SM_PART + NGRP * TB * NN * 8)  // 69888

// ---------------------------------------------------------------------------
// Main: 147 CTAs x 1024 threads = 4 i-groups of 256 j-threads.
// Group ig accumulates over pre-neurons i in [ig*64, ig*64+64) for ALL 7
// batches (param reads disjoint across groups -> no duplicated traffic).
// Partials merged via 4-slot SMEM buffer; group ig owns batches 2*ig..(+1).
// ---------------------------------------------------------------------------
__global__ void __launch_bounds__(1024, 1) k_main(const float* __restrict__ inputs,
                                                  const float* __restrict__ state,
                                                  float* __restrict__ out) {
    extern __shared__ char smem[];
    float  (*v_f)[NN]       = reinterpret_cast<float (*)[NN]>(smem + SM_VF);
    __half (*v_h)[NN]       = reinterpret_cast<__half (*)[NN]>(smem + SM_VH);
    float  (*xin)[SS]       = reinterpret_cast<float (*)[SS]>(smem + SM_XIN);
    float2 (*part)[TB][NN]  = reinterpret_cast<float2 (*)[TB][NN]>(smem + SM_PART);

    int tid = threadIdx.x;
    int ig  = tid >> 8;          // 0..3
    int j   = tid & 255;
    int b0  = blockIdx.x * TB;
    int ob      = ig * 2;                 // first owned batch
    int own_cnt = (ig == 3) ? 1 : 2;

    // inputs: 7 rows x 64 = 448 floats (clamped for the edge CTA)
    if (tid < TB * SS) xin[tid >> 6][tid & 63] = inputs[min(b0 * SS + tid, BB * SS - 1)];

    // state: 1792 floats (clamped)
    for (int idx = tid; idx < TB * NN; idx += 1024) {
        float v = state[min(b0 * NN + idx, BB * NN - 1)];
        int bb = idx >> 8, jj = idx & 255;
        v_f[bb][jj] = v;
        v_h[bb][jj] = __float2half_rn(v);
    }
    __syncthreads();

    // --- sensory pass (step-invariant) for owned batches (<=2) ---
    float ncr[2], dcr[2];
    {
        float sn[2] = {0.f, 0.f}, sd[2] = {0.f, 0.f};
        #pragma unroll 2
        for (int s = 0; s < SS; s++) {
            float4 q = g_sparams[s * NN + j];
            #pragma unroll
            for (int k = 0; k < 2; k++) {
                int bx = ob + min(k, own_cnt - 1);   // clamp keeps loop uniform
                float t  = tanh_fast(fmaf(q.x, xin[bx][s], q.y));
                float sg = fmaf(0.5f, t, 0.5f);
                sn[k] = fmaf(q.z, sg, sn[k]);
                sd[k] = fmaf(q.w, sg, sd[k]);
            }
        }
        float gv = g_gv[j], she = g_sum_hwe[j], gl = g_gl[j], shw = g_sum_hw[j];
        float cmt0 = g_cmt[j];
        #pragma unroll
        for (int k = 0; k < 2; k++) {
            ncr[k] = gv + she + sn[k];
            dcr[k] = cmt0 + gl + shw + sd[k] + 1e-8f;
        }
    }
    float cmt = g_cmt[j];

    const int Q0 = ig * QPG;            // first quad of this group
    const int P0 = ig * (NPAIR / NGRP); // first pair
    const int ibase = ig * (NN / NGRP); // first pre-neuron
    const uint4*  ABQ = g_abq + Q0 * NN + j;
    const uint4*  W16 = g_w16 + Q0 * NN + j;
    const float4* WEQ = g_weq + Q0 * NN + j;
    const float4* ABF = g_abf + P0 * NN + j;

    for (int step = 0; step < UNFOLDS; step++) {
        float num[TB], den[TB];
        #pragma unroll
        for (int b = 0; b < TB; b++) { num[b] = 0.f; den[b] = 0.f; }

        if (step < FAST_STEPS) {
            // ---------- fast f16x2 path: 8 blocks of 8 i's ----------
            for (int blk = 0; blk < FBLK; blk++) {
                uint4 cab0 = ABQ[(blk * 2    ) * NN];
                uint4 cab1 = ABQ[(blk * 2 + 1) * NN];
                uint4 cw0  = W16[(blk * 2    ) * NN];
                uint4 cw1  = W16[(blk * 2 + 1) * NN];
                #pragma unroll
                for (int b = 0; b < TB; b++) {
                    uint4 vh = *reinterpret_cast<const uint4*>(&v_h[b][ibase + blk * 8]);
                    proc_block16(vh, cab0, cab1, cw0, cw1, num[b], den[b]);
                }
            }
        } else {
            // ---------- accurate fp32 path (last step): 16 quads ----------
            #pragma unroll 2
            for (int q = 0; q < QPG; q++) {
                float4 a0 = ABF[(q * 2) * NN];
                float4 a1 = ABF[(q * 2 + 1) * NN];
                float4 e  = WEQ[q * NN];
                #pragma unroll
                for (int b = 0; b < TB; b++) {
                    float4 v = *reinterpret_cast<const float4*>(&v_f[b][ibase + q * 4]);
                    float t0 = tanh_fast(fmaf(a0.x, v.x, a0.z));
                    float t1 = tanh_fast(fmaf(a0.y, v.y, a0.w));
                    float t2 = tanh_fast(fmaf(a1.x, v.z, a1.z));
                    float t3 = tanh_fast(fmaf(a1.y, v.w, a1.w));
                    num[b] = fmaf(e.x, t0, num[b]); den[b] = fmaf(fabsf(e.x), t0, den[b]);
                    num[b] = fmaf(e.y, t1, num[b]); den[b] = fmaf(fabsf(e.y), t1, den[b]);
                    num[b] = fmaf(e.z, t2, num[b]); den[b] = fmaf(fabsf(e.z), t2, den[b]);
                    num[b] = fmaf(e.w, t3, num[b]); den[b] = fmaf(fabsf(e.w), t3, den[b]);
                }
            }
        }

        // every group writes all its partials to its slot
        #pragma unroll
        for (int b = 0; b < TB; b++)
            part[ig][b][j] = make_float2(num[b], den[b]);
        __syncthreads();

        // owners merge 4 partials and update state
        #pragma unroll
        for (int k = 0; k < 2; k++) {
            if (k < own_cnt) {
                int b = ob + k;
                float2 p0 = part[0][b][j];
                float2 p1 = part[1][b][j];
                float2 p2 = part[2][b][j];
                float2 p3 = part[3][b][j];
                float n = (p0.x + p1.x) + (p2.x + p3.x);
                float d = (p0.y + p1.y) + (p2.y + p3.y);
                float vn = (fmaf(cmt, v_f[b][j], ncr[k]) + n) / (d + dcr[k]);
                v_f[b][j] = vn;
                v_h[b][j] = __float2half_rn(vn);
            }
        }
        __syncthreads();
    }

    // owner writes its rows (guarded for the edge CTA)
    #pragma unroll
    for (int k = 0; k < 2; k++) {
        if (k < own_cnt) {
            int b = ob + k;
            if (b0 + b < BB) out[(b0 + b) * NN + j] = v_f[b][j];
        }
    }
}

extern "C" void kernel_launch(void* const* d_in, const int* in_sizes, int n_in,
                              void* d_out, int out_size) {
    const float* inputs = (const float*)d_in[0];
    const float* state  = (const float*)d_in[1];
    const float* gleak  = (const float*)d_in[2];
    const float* vleak  = (const float*)d_in[3];
    const float* cm     = (const float*)d_in[4];
    const float* w      = (const float*)d_in[5];
    const float* sigma  = (const float*)d_in[6];
    const float* mu     = (const float*)d_in[7];
    const float* erev   = (const float*)d_in[8];
    const float* sw     = (const float*)d_in[9];
    const float* ssig   = (const float*)d_in[10];
    const float* smu    = (const float*)d_in[11];
    const float* serev  = (const float*)d_in[12];
    const float* mask   = (const float*)d_in[13];
    const float* smask  = (const float*)d_in[14];
    float* out = (float*)d_out;

    cudaFuncSetAttribute(k_main, cudaFuncAttributeMaxDynamicSharedMemorySize, SM_TOTAL);

    k_prep   <<<NQUAD, NN>>>(w, sigma, mu, erev, mask);
    k_sprep  <<<SS, NN>>>(sw, ssig, smu, serev, smask);
    k_colsums<<<1,  NN>>>(gleak, vleak, cm);
    k_main   <<<GRID, 1024, SM_TOTAL>>>(inputs, state, out);
}